// round 7
// baseline (speedup 1.0000x reference)
#include <cuda_runtime.h>
#include <cstdint>

#define HID 128
#define ENC_T 8192
#define DEC_T 4096
#define CLUSTER 4
#define TPB 128   // lane = (unit 0..31)<<2 | (gate 0..3)

__device__ __forceinline__ uint32_t smem_u32(const void* p) {
    return (uint32_t)__cvta_generic_to_shared(p);
}

__device__ __forceinline__ uint32_t mapa_(uint32_t laddr, uint32_t rank) {
    uint32_t r;
    asm("mapa.shared::cluster.u32 %0, %1, %2;" : "=r"(r) : "r"(laddr), "r"(rank));
    return r;
}

__device__ __forceinline__ float sigm_(float x) { return 1.0f / (1.0f + __expf(-x)); }
__device__ __forceinline__ float tanh_(float x) { return 1.0f - 2.0f / (__expf(2.0f * x) + 1.0f); }

// 128-term dot: per-lane packed-f32x2 weights vs broadcast h in SMEM.
__device__ __forceinline__ float dot128(const unsigned long long* w2, uint32_t haddr) {
    unsigned long long a0 = 0ull, a1 = 0ull, a2 = 0ull, a3 = 0ull;
    #pragma unroll
    for (int j = 0; j < 16; j++) {
        unsigned long long h01, h23, h45, h67;
        asm volatile("ld.shared.v2.b64 {%0,%1},[%2];"
                     : "=l"(h01), "=l"(h23) : "r"(haddr + j * 32));
        asm volatile("ld.shared.v2.b64 {%0,%1},[%2];"
                     : "=l"(h45), "=l"(h67) : "r"(haddr + j * 32 + 16));
        asm("fma.rn.f32x2 %0,%1,%2,%0;" : "+l"(a0) : "l"(w2[4 * j + 0]), "l"(h01));
        asm("fma.rn.f32x2 %0,%1,%2,%0;" : "+l"(a1) : "l"(w2[4 * j + 1]), "l"(h23));
        asm("fma.rn.f32x2 %0,%1,%2,%0;" : "+l"(a2) : "l"(w2[4 * j + 2]), "l"(h45));
        asm("fma.rn.f32x2 %0,%1,%2,%0;" : "+l"(a3) : "l"(w2[4 * j + 3]), "l"(h67));
    }
    asm("add.rn.f32x2 %0,%0,%1;" : "+l"(a0) : "l"(a2));
    asm("add.rn.f32x2 %0,%0,%1;" : "+l"(a1) : "l"(a3));
    asm("add.rn.f32x2 %0,%0,%1;" : "+l"(a0) : "l"(a1));
    float lo, hi;
    asm("mov.b64 {%0,%1},%2;" : "=f"(lo), "=f"(hi) : "l"(a0));
    return lo + hi;
}

// Poll 4 consecutive {h,tag} slots (32B at 'addr') until all tags == s.
// Returns the 4 h bit-patterns.
__device__ __forceinline__ void poll4(uint32_t addr, int s,
                                      uint32_t& h0, uint32_t& h1,
                                      uint32_t& h2, uint32_t& h3) {
    int t0, t1, t2, t3;
    do {
        unsigned long long q0, q1, q2, q3;
        asm volatile("ld.volatile.shared.v2.b64 {%0,%1},[%2];"
                     : "=l"(q0), "=l"(q1) : "r"(addr));
        asm volatile("ld.volatile.shared.v2.b64 {%0,%1},[%2];"
                     : "=l"(q2), "=l"(q3) : "r"(addr + 16));
        asm("mov.b64 {%0,%1},%2;" : "=r"(h0), "=r"(t0) : "l"(q0));
        asm("mov.b64 {%0,%1},%2;" : "=r"(h1), "=r"(t1) : "l"(q1));
        asm("mov.b64 {%0,%1},%2;" : "=r"(h2), "=r"(t2) : "l"(q2));
        asm("mov.b64 {%0,%1},%2;" : "=r"(h3), "=r"(t3) : "l"(q3));
    } while (((t0 ^ s) | (t1 ^ s) | (t2 ^ s) | (t3 ^ s)) != 0);
}

__device__ __forceinline__ void warpsync_() {
    asm volatile("bar.warp.sync 0xffffffff;" ::: "memory");
}

// fcW . h from per-lane 4-term partials + 5-level xor reduce (all lanes get result)
__device__ __forceinline__ float warp_fcdot(const float* fcw4,
                                            uint32_t h0, uint32_t h1,
                                            uint32_t h2, uint32_t h3) {
    float v = fcw4[0] * __uint_as_float(h0) + fcw4[1] * __uint_as_float(h1)
            + fcw4[2] * __uint_as_float(h2) + fcw4[3] * __uint_as_float(h3);
    #pragma unroll
    for (int o = 16; o > 0; o >>= 1) v += __shfl_xor_sync(0xffffffffu, v, o);
    return v;
}

__global__ void __cluster_dims__(CLUSTER, 1, 1) __launch_bounds__(TPB, 1)
seq2seq_kernel(const float* __restrict__ input_seq,
               const float* __restrict__ enc_Wih, const float* __restrict__ enc_Whh,
               const float* __restrict__ enc_bih, const float* __restrict__ enc_bhh,
               const float* __restrict__ dec_Wih, const float* __restrict__ dec_Whh,
               const float* __restrict__ dec_bih, const float* __restrict__ dec_bhh,
               const float* __restrict__ fc_W,    const float* __restrict__ fc_b,
               float* __restrict__ out)
{
    __shared__ float xs[ENC_T];                                // 32 KB input sequence
    __shared__ __align__(16) unsigned long long pkbuf[2][HID]; // {h:f32, tag:s32} delivery slots
    __shared__ __align__(16) float hw_all[4][HID];             // per-WARP private h copies

    const int tid  = threadIdx.x;
    uint32_t rank;
    asm("mov.u32 %0, %%cluster_ctarank;" : "=r"(rank));
    const int unit  = tid >> 2;
    const int gate  = tid & 3;                 // i,f,g,o ; also = delivery-target CTA
    const int gunit = (int)rank * 32 + unit;   // global unit this lane-group owns
    const int row   = gate * HID + gunit;
    const int wid   = tid >> 5;
    const int lane  = tid & 31;
    const unsigned FULL = 0xffffffffu;
    const int base = lane & ~3;

    for (int i = tid; i < ENC_T; i += TPB) xs[i] = input_seq[i];
    if (tid < HID) { pkbuf[0][tid] = 0ull; pkbuf[1][tid] = 0ull; }
    const float fcb = fc_b[0];
    float fcw4[4];
    #pragma unroll
    for (int k = 0; k < 4; k++) fcw4[k] = fc_W[lane * 4 + k];

    // hoisted addresses
    const uint32_t pkb[2]   = { smem_u32(pkbuf[0]), smem_u32(pkbuf[1]) };
    const uint32_t pollb[2] = { pkb[0] + lane * 32, pkb[1] + lane * 32 };  // my 4 poll slots
    const uint32_t rpk[2]   = { mapa_(pkb[0] + gunit * 8, (uint32_t)gate),
                                mapa_(pkb[1] + gunit * 8, (uint32_t)gate) };
    const uint32_t hbw   = smem_u32(&hw_all[wid][0]);      // this warp's h copy
    const uint32_t hmine = hbw + lane * 16;

    unsigned long long w2[64];                 // this lane's 128 weights, packed f32x2
    #pragma unroll
    for (int j = 0; j < 64; j++) {
        float a = enc_Whh[row * HID + 2 * j];
        float b = enc_Whh[row * HID + 2 * j + 1];
        asm("mov.b64 %0,{%1,%2};" : "=l"(w2[j]) : "f"(a), "f"(b));
    }
    float btot = enc_bih[row] + enc_bhh[row];
    float wihr = enc_Wih[row];

    float c = 0.0f;                            // cell state (replicated in the 4 gate lanes)

    __syncthreads();
    asm volatile("barrier.cluster.arrive.aligned;" ::: "memory");
    asm volatile("barrier.cluster.wait.aligned;"   ::: "memory");

    // ---------------- encoder: steps s = 0 .. ENC_T-1 ----------------
    #pragma unroll 1
    for (int s = 0; s < ENC_T; ++s) {
        const int p = s & 1, np = p ^ 1;
        const float ai = fmaf(wihr, xs[s], btot);

        uint32_t h0, h1, h2, h3;
        poll4(pollb[p], s, h0, h1, h2, h3);
        asm volatile("st.shared.v4.b32 [%0],{%1,%2,%3,%4};"
                     :: "r"(hmine), "r"(h0), "r"(h1), "r"(h2), "r"(h3) : "memory");
        warpsync_();                           // warp-local only: no remote-store drain

        float acc = dot128(w2, hbw) + ai;
        const float a  = (gate == 2) ? tanh_(acc) : sigm_(acc);
        const float gi = __shfl_sync(FULL, a, base + 0);
        const float gf = __shfl_sync(FULL, a, base + 1);
        const float gg = __shfl_sync(FULL, a, base + 2);
        const float go = __shfl_sync(FULL, a, base + 3);
        c = gf * c + gi * gg;
        const float hn = go * tanh_(c);

        unsigned long long pkt;
        asm("mov.b64 %0,{%1,%2};" : "=l"(pkt) : "f"(hn), "r"(s + 1));
        asm volatile("st.shared::cluster.b64 [%0],%1;" :: "r"(rpk[np]), "l"(pkt) : "memory");
    }

    // ---------------- decoder weights: fold fc_W/fc_b into Whh/bias ----------------
    // W.h + wih*(fcW.h + fcb) + b == (W + wih*fcW^T).h + (b + wih*fcb)
    wihr = dec_Wih[row];
    #pragma unroll
    for (int j = 0; j < 64; j++) {
        float a = fmaf(wihr, fc_W[2 * j],     dec_Whh[row * HID + 2 * j]);
        float b = fmaf(wihr, fc_W[2 * j + 1], dec_Whh[row * HID + 2 * j + 1]);
        asm("mov.b64 %0,{%1,%2};" : "=l"(w2[j]) : "f"(a), "f"(b));
    }
    const float btot_pl   = dec_bih[row] + dec_bhh[row];
    const float btot_fold = fmaf(wihr, fcb, btot_pl);
    const bool emitter = (rank == 0) && (wid == 0);

    // ---------------- decoder: steps s = ENC_T .. ENC_T+DEC_T-1 ----------------
    #pragma unroll 1
    for (int d = 0; d < DEC_T; ++d) {
        const int s = ENC_T + d;
        const int p = s & 1, np = p ^ 1;

        uint32_t h0, h1, h2, h3;
        poll4(pollb[p], s, h0, h1, h2, h3);
        asm volatile("st.shared.v4.b32 [%0],{%1,%2,%3,%4};"
                     :: "r"(hmine), "r"(h0), "r"(h1), "r"(h2), "r"(h3) : "memory");
        warpsync_();

        float ai;
        if (d == 0) {
            // first step must see y = 0: subtract the folded-in fcW.h_enc term
            const float q = warp_fcdot(fcw4, h0, h1, h2, h3);
            ai = btot_pl - wihr * q;
        } else {
            ai = btot_fold;
        }

        float acc = dot128(w2, hbw) + ai;
        const float a  = (gate == 2) ? tanh_(acc) : sigm_(acc);
        const float gi = __shfl_sync(FULL, a, base + 0);
        const float gf = __shfl_sync(FULL, a, base + 1);
        const float gg = __shfl_sync(FULL, a, base + 2);
        const float go = __shfl_sync(FULL, a, base + 3);
        c = gf * c + gi * gg;
        const float hn = go * tanh_(c);

        unsigned long long pkt;
        asm("mov.b64 %0,{%1,%2};" : "=l"(pkt) : "f"(hn), "r"(s + 1));
        asm volatile("st.shared::cluster.b64 [%0],%1;" :: "r"(rpk[np]), "l"(pkt) : "memory");

        // post-store emission: hidden under the next step's DSMEM transit wait.
        // pred_{d-1} = fcW . h(s) + fcb, from this step's polled h (still in regs).
        if (emitter && d >= 1) {
            const float v = warp_fcdot(fcw4, h0, h1, h2, h3);
            if (lane == 0) out[d - 1] = v + fcb;
        }
    }

    // final prediction: h(ENC_T+DEC_T) lands in parity-0 slots with tag ENC_T+DEC_T
    if (emitter) {
        uint32_t h0, h1, h2, h3;
        poll4(pollb[0], ENC_T + DEC_T, h0, h1, h2, h3);
        const float v = warp_fcdot(fcw4, h0, h1, h2, h3);
        if (lane == 0) out[DEC_T - 1] = v + fcb;
    }

    // keep every CTA alive until all peers' remote stores into our SMEM landed
    asm volatile("barrier.cluster.arrive.aligned;" ::: "memory");
    asm volatile("barrier.cluster.wait.aligned;"   ::: "memory");
}

extern "C" void kernel_launch(void* const* d_in, const int* in_sizes, int n_in,
                              void* d_out, int out_size) {
    (void)in_sizes; (void)n_in; (void)out_size;
    seq2seq_kernel<<<CLUSTER, TPB>>>(
        (const float*)d_in[0],
        (const float*)d_in[1], (const float*)d_in[2],
        (const float*)d_in[3], (const float*)d_in[4],
        (const float*)d_in[5], (const float*)d_in[6],
        (const float*)d_in[7], (const float*)d_in[8],
        (const float*)d_in[9], (const float*)d_in[10],
        (float*)d_out);
}

// round 8
// speedup vs baseline: 3.0596x; 3.0596x over previous
#include <cuda_runtime.h>
#include <cstdint>

#define HID 128
#define ENC_T 8192
#define DEC_T 4096
#define CLUSTER 4
#define TPB 128   // lane = (unit 0..31)<<2 | (gate 0..3)

__device__ __forceinline__ uint32_t smem_u32(const void* p) {
    return (uint32_t)__cvta_generic_to_shared(p);
}

__device__ __forceinline__ uint32_t mapa_(uint32_t laddr, uint32_t rank) {
    uint32_t r;
    asm("mapa.shared::cluster.u32 %0, %1, %2;" : "=r"(r) : "r"(laddr), "r"(rank));
    return r;
}

__device__ __forceinline__ float tanh_(float x) {
    // tanh(x) = 1 - 2/(exp(2x)+1); saturates correctly at +-inf
    return 1.0f - 2.0f / (__expf(2.0f * x) + 1.0f);
}

// 128-term dot: per-lane packed-f32x2 weights vs broadcast h in SMEM.
// a0 is initialized with {ainit, 0} so the bias/input term rides for free.
__device__ __forceinline__ float dot128(const unsigned long long* w2, uint32_t haddr,
                                        float ainit) {
    unsigned long long a0, a1 = 0ull, a2 = 0ull, a3 = 0ull;
    asm("mov.b64 %0,{%1,%2};" : "=l"(a0) : "f"(ainit), "f"(0.0f));
    #pragma unroll
    for (int j = 0; j < 16; j++) {
        unsigned long long h01, h23, h45, h67;
        asm volatile("ld.shared.v2.b64 {%0,%1},[%2];"
                     : "=l"(h01), "=l"(h23) : "r"(haddr + j * 32));
        asm volatile("ld.shared.v2.b64 {%0,%1},[%2];"
                     : "=l"(h45), "=l"(h67) : "r"(haddr + j * 32 + 16));
        asm("fma.rn.f32x2 %0,%1,%2,%0;" : "+l"(a0) : "l"(w2[4 * j + 0]), "l"(h01));
        asm("fma.rn.f32x2 %0,%1,%2,%0;" : "+l"(a1) : "l"(w2[4 * j + 1]), "l"(h23));
        asm("fma.rn.f32x2 %0,%1,%2,%0;" : "+l"(a2) : "l"(w2[4 * j + 2]), "l"(h45));
        asm("fma.rn.f32x2 %0,%1,%2,%0;" : "+l"(a3) : "l"(w2[4 * j + 3]), "l"(h67));
    }
    asm("add.rn.f32x2 %0,%0,%1;" : "+l"(a0) : "l"(a2));
    asm("add.rn.f32x2 %0,%0,%1;" : "+l"(a1) : "l"(a3));
    asm("add.rn.f32x2 %0,%0,%1;" : "+l"(a0) : "l"(a1));
    float lo, hi;
    asm("mov.b64 {%0,%1},%2;" : "=f"(lo), "=f"(hi) : "l"(a0));
    return lo + hi;
}

__global__ void __cluster_dims__(CLUSTER, 1, 1) __launch_bounds__(TPB, 1)
seq2seq_kernel(const float* __restrict__ input_seq,
               const float* __restrict__ enc_Wih, const float* __restrict__ enc_Whh,
               const float* __restrict__ enc_bih, const float* __restrict__ enc_bhh,
               const float* __restrict__ dec_Wih, const float* __restrict__ dec_Whh,
               const float* __restrict__ dec_bih, const float* __restrict__ dec_bhh,
               const float* __restrict__ fc_W,    const float* __restrict__ fc_b,
               float* __restrict__ out)
{
    __shared__ float xs[ENC_T];                               // 32 KB input sequence
    __shared__ __align__(16) float hbuf[2][HID];              // local contiguous h copy (per parity)
    __shared__ __align__(16) unsigned long long pkbuf[2][HID];// {h:f32, tag:s32} delivery slots
    __shared__ float fcW_sm[HID];
    __shared__ float qpart[4];

    const int tid  = threadIdx.x;
    uint32_t rank;
    asm("mov.u32 %0, %%cluster_ctarank;" : "=r"(rank));
    const int unit  = tid >> 2;
    const int gate  = tid & 3;                 // i,f,g,o ; also = delivery-target CTA
    const int gunit = (int)rank * 32 + unit;   // global unit this lane-group owns
    const int row   = gate * HID + gunit;
    const int wid   = tid >> 5;
    const int lane  = tid & 31;
    const unsigned FULL = 0xffffffffu;
    const int base = lane & ~3;

    // Branchless activation constants:
    //   sigmoid lanes: a = 1/(1+exp(-x))          -> am=-1, ak=1, ab=0
    //   tanh lane (g): a = 2/(1+exp(-2x)) - 1     -> am=-2, ak=2, ab=-1
    const float am = (gate == 2) ? -2.0f : -1.0f;
    const float ak = (gate == 2) ?  2.0f :  1.0f;
    const float ab = (gate == 2) ? -1.0f :  0.0f;

    for (int i = tid; i < ENC_T; i += TPB) xs[i] = input_seq[i];
    if (tid < HID) { fcW_sm[tid] = fc_W[tid]; pkbuf[0][tid] = 0ull; pkbuf[1][tid] = 0ull; }
    const float fcb = fc_b[0];

    // hoisted addresses
    const uint32_t hb[2]   = { smem_u32(hbuf[0]), smem_u32(hbuf[1]) };
    const uint32_t pkb[2]  = { smem_u32(pkbuf[0]), smem_u32(pkbuf[1]) };
    const uint32_t slot[2] = { pkb[0] + tid * 8, pkb[1] + tid * 8 };   // my poll slot (unit = tid)
    const uint32_t hloc[2] = { hb[0] + tid * 4, hb[1] + tid * 4 };
    const uint32_t rpk[2]  = { mapa_(pkb[0] + gunit * 8, (uint32_t)gate),
                               mapa_(pkb[1] + gunit * 8, (uint32_t)gate) };

    unsigned long long w2[64];                 // this lane's 128 weights, packed f32x2
    #pragma unroll
    for (int j = 0; j < 64; j++) {
        float a = enc_Whh[row * HID + 2 * j];
        float b = enc_Whh[row * HID + 2 * j + 1];
        asm("mov.b64 %0,{%1,%2};" : "=l"(w2[j]) : "f"(a), "f"(b));
    }
    float btot = enc_bih[row] + enc_bhh[row];
    float wihr = enc_Wih[row];

    float c = 0.0f;                            // cell state (replicated in the 4 gate lanes)

    __syncthreads();
    asm volatile("barrier.cluster.arrive.aligned;" ::: "memory");
    asm volatile("barrier.cluster.wait.aligned;"   ::: "memory");

    // ---------------- encoder: steps s = 0 .. ENC_T-1 ----------------
    #pragma unroll 1
    for (int s = 0; s < ENC_T; ++s) {
        const int p = s & 1, np = p ^ 1;
        const float ai = fmaf(wihr, xs[s], btot);

        // single-8B-atomic handshake: tag==s implies h(s) is in the same word.
        // unrolled x2 to shorten the poll period.
        uint32_t hv; int tg;
        while (true) {
            asm volatile("ld.volatile.shared.v2.b32 {%0,%1},[%2];"
                         : "=r"(hv), "=r"(tg) : "r"(slot[p]));
            if (tg == s) break;
            asm volatile("ld.volatile.shared.v2.b32 {%0,%1},[%2];"
                         : "=r"(hv), "=r"(tg) : "r"(slot[p]));
            if (tg == s) break;
        }
        asm volatile("st.shared.b32 [%0],%1;" :: "r"(hloc[p]), "r"(hv) : "memory");
        __syncthreads();                       // drains STS; all 128 h gathered

        const float acc = dot128(w2, hb[p], ai);
        // branchless activation: all lanes run one sigmoid chain
        const float a  = fmaf(ak, 1.0f / (1.0f + __expf(am * acc)), ab);
        const float gi = __shfl_sync(FULL, a, base + 0);
        const float gf = __shfl_sync(FULL, a, base + 1);
        const float gg = __shfl_sync(FULL, a, base + 2);
        const float go = __shfl_sync(FULL, a, base + 3);
        c = gf * c + gi * gg;
        const float hn = go * tanh_(c);

        unsigned long long pkt;
        asm("mov.b64 %0,{%1,%2};" : "=l"(pkt) : "f"(hn), "r"(s + 1));
        asm volatile("st.shared::cluster.b64 [%0],%1;" :: "r"(rpk[np]), "l"(pkt) : "memory");
    }

    // ---------------- decoder weights: fold fc_W/fc_b into Whh/bias ----------------
    // W.h + wih*(fcW.h + fcb) + b == (W + wih*fcW^T).h + (b + wih*fcb)
    wihr = dec_Wih[row];
    #pragma unroll
    for (int j = 0; j < 64; j++) {
        float a = fmaf(wihr, fcW_sm[2 * j],     dec_Whh[row * HID + 2 * j]);
        float b = fmaf(wihr, fcW_sm[2 * j + 1], dec_Whh[row * HID + 2 * j + 1]);
        asm("mov.b64 %0,{%1,%2};" : "=l"(w2[j]) : "f"(a), "f"(b));
    }
    const float btot_pl   = dec_bih[row] + dec_bhh[row];
    const float btot_fold = fmaf(wihr, fcb, btot_pl);

    // fc weights for the out-emitter (rank0 warp0); harmless elsewhere
    const float f0 = fcW_sm[lane], f1 = fcW_sm[lane + 32],
                f2 = fcW_sm[lane + 64], f3 = fcW_sm[lane + 96];
    const bool emitter = (rank == 0) && (wid == 0);

    // ---------------- decoder: steps s = ENC_T .. ENC_T+DEC_T-1 ----------------
    #pragma unroll 1
    for (int d = 0; d < DEC_T; ++d) {
        const int s = ENC_T + d;
        const int p = s & 1, np = p ^ 1;

        uint32_t hv; int tg;
        while (true) {
            asm volatile("ld.volatile.shared.v2.b32 {%0,%1},[%2];"
                         : "=r"(hv), "=r"(tg) : "r"(slot[p]));
            if (tg == s) break;
            asm volatile("ld.volatile.shared.v2.b32 {%0,%1},[%2];"
                         : "=r"(hv), "=r"(tg) : "r"(slot[p]));
            if (tg == s) break;
        }
        asm volatile("st.shared.b32 [%0],%1;" :: "r"(hloc[p]), "r"(hv) : "memory");
        __syncthreads();

        float ai;
        if (d == 0) {
            // first step must see y = 0: subtract the folded-in fcW.h_enc term
            float pq = fcW_sm[tid] * hbuf[p][tid];
            #pragma unroll
            for (int o = 1; o < 32; o <<= 1) pq += __shfl_xor_sync(FULL, pq, o);
            if (lane == 0) qpart[wid] = pq;
            __syncthreads();
            const float q = (qpart[0] + qpart[1]) + (qpart[2] + qpart[3]);
            ai = btot_pl - wihr * q;
        } else {
            ai = btot_fold;
        }

        const float acc = dot128(w2, hb[p], ai);
        const float a  = fmaf(ak, 1.0f / (1.0f + __expf(am * acc)), ab);
        const float gi = __shfl_sync(FULL, a, base + 0);
        const float gf = __shfl_sync(FULL, a, base + 1);
        const float gg = __shfl_sync(FULL, a, base + 2);
        const float go = __shfl_sync(FULL, a, base + 3);
        c = gf * c + gi * gg;
        const float hn = go * tanh_(c);

        unsigned long long pkt;
        asm("mov.b64 %0,{%1,%2};" : "=l"(pkt) : "f"(hn), "r"(s + 1));
        asm volatile("st.shared::cluster.b64 [%0],%1;" :: "r"(rpk[np]), "l"(pkt) : "memory");

        // post-store emission (hidden under next step's DSMEM transit wait):
        // pred_{d-1} = fcW . h(s) + fcb from the local h copy
        if (emitter && d >= 1) {
            float v = f0 * hbuf[p][lane] + f1 * hbuf[p][lane + 32]
                    + f2 * hbuf[p][lane + 64] + f3 * hbuf[p][lane + 96];
            #pragma unroll
            for (int o = 16; o > 0; o >>= 1) v += __shfl_xor_sync(FULL, v, o);
            if (lane == 0) out[d - 1] = v + fcb;
        }
    }

    // final prediction: h(ENC_T+DEC_T) sits in parity-0 slots with tag ENC_T+DEC_T
    if (rank == 0) {
        uint32_t hv; int tg;
        do {
            asm volatile("ld.volatile.shared.v2.b32 {%0,%1},[%2];"
                         : "=r"(hv), "=r"(tg) : "r"(slot[0]));
        } while (tg != ENC_T + DEC_T);
        asm volatile("st.shared.b32 [%0],%1;" :: "r"(hloc[0]), "r"(hv) : "memory");
        __syncthreads();
        if (wid == 0) {
            float v = f0 * hbuf[0][lane] + f1 * hbuf[0][lane + 32]
                    + f2 * hbuf[0][lane + 64] + f3 * hbuf[0][lane + 96];
            #pragma unroll
            for (int o = 16; o > 0; o >>= 1) v += __shfl_xor_sync(FULL, v, o);
            if (lane == 0) out[DEC_T - 1] = v + fcb;
        }
    }

    // keep every CTA alive until all peers' remote stores into our SMEM landed
    asm volatile("barrier.cluster.arrive.aligned;" ::: "memory");
    asm volatile("barrier.cluster.wait.aligned;"   ::: "memory");
}

extern "C" void kernel_launch(void* const* d_in, const int* in_sizes, int n_in,
                              void* d_out, int out_size) {
    (void)in_sizes; (void)n_in; (void)out_size;
    seq2seq_kernel<<<CLUSTER, TPB>>>(
        (const float*)d_in[0],
        (const float*)d_in[1], (const float*)d_in[2],
        (const float*)d_in[3], (const float*)d_in[4],
        (const float*)d_in[5], (const float*)d_in[6],
        (const float*)d_in[7], (const float*)d_in[8],
        (const float*)d_in[9], (const float*)d_in[10],
        (float*)d_out);
}